// round 11
// baseline (speedup 1.0000x reference)
#include <cuda_runtime.h>
#include <math.h>

// ANI AEV computer. M=32, A=48, S=4.
// Radial: 4 species x 16 ShfR = 64 ch. Angular: 10 sp-pairs x 4 ShfA x 8 ShfZ = 320 ch.
// Output (32, 48, 384) fp32.
//
// R7 (15.0us): bucketed gather for angular (zero angular atomics).
// R8 (14.0us): Gaussian-ladder exp factorization (MUFU cut ~3x).
// R9 (12.8us): shared pair list, vectorized prologue, fewer syncs.
// R10: 2 central atoms per block (grid 768): prologue amortized 2x, radial
//      96/128 threads, Phase A ~90/128, Phase B 5 channels/thread with
//      shared iz/ia across slots (128 = 0 mod 32). 20 buckets (atom x pidx).

#define MM 32
#define AA 48
#define SS 4
#define NATB 2                                     // central atoms per block
#define NSHFR 16
#define NSHFA 4
#define NSHFZ 8
#define RAD_SUB 16
#define ANG_SUB 32
#define NPAIRS_SP 10
#define NANG (NPAIRS_SP * ANG_SUB)                 // 320
#define OUT_PER_ATOM (SS * RAD_SUB + NANG)         // 384
#define RCR_F 5.2f
#define RCA_F 3.5f
#define NTHREADS 128
#define NBUCK (NATB * NPAIRS_SP)                   // 20
#define MAXPAIR 2176                               // 2 * 47*46/2 rounded up

__global__ __launch_bounds__(NTHREADS)
void aev_kernel(const float* __restrict__ coords,
                const float* __restrict__ EtaR,
                const float* __restrict__ ShfR,
                const float* __restrict__ EtaA,
                const float* __restrict__ Zeta,
                const float* __restrict__ ShfA,
                const float* __restrict__ ShfZ,
                const int*   __restrict__ species,
                float*       __restrict__ out)
{
    const int m   = blockIdx.x / (AA / NATB);
    const int cb  = (blockIdx.x % (AA / NATB)) * NATB;   // first central atom
    const int tid = threadIdx.x;

    __shared__ float scrd[AA * 3];
    __shared__ int   ssp[AA];
    __shared__ float accR[NATB][SS * RAD_SUB];
    __shared__ float shfR[NSHFR], shfA_s[NSHFA];
    __shared__ float cz2[NSHFZ], sz2[NSHFZ];
    __shared__ int   ptab[SS * SS];
    __shared__ float s_etaR, s_etaA, s_zeta;
    __shared__ int   nnb[NATB];
    __shared__ float nbd[NATB][AA], nbx[NATB][AA], nby[NATB][AA], nbz[NATB][AA], nbfc[NATB][AA];
    __shared__ int   nbsp[NATB][AA];
    // ladder ratio tables
    __shared__ float cuR[NSHFR - 1], cdR[NSHFR - 1];
    __shared__ float cauA[NSHFA - 1];
    __shared__ float s_invdR, s_2edR, s_2edA;
    // pair list + per-tile records + buckets
    __shared__ unsigned short ppair[MAXPAIR];
    __shared__ int   s_npair0;
    __shared__ float pc[NTHREADS], psn[NTHREADS];
    __shared__ float pf2[NTHREADS][NSHFA];
    __shared__ int   blist[NBUCK][NTHREADS];
    __shared__ int   bcnt[NBUCK];

    // ---- vectorized prologue loads + table init ----
    if (tid < 36)
        ((float4*)scrd)[tid] = ((const float4*)(coords + m * AA * 3))[tid];
    if (tid >= 40 && tid < 52)
        ((int4*)ssp)[tid - 40] = ((const int4*)(species + m * AA))[tid - 40];
    if (tid < NSHFR) shfR[tid] = ShfR[tid];
    if (tid < NSHFA) shfA_s[tid] = ShfA[tid];
    if (tid < NSHFZ) {
        float s = ShfZ[tid];
        cz2[tid] = 0.5f * cosf(s);
        sz2[tid] = 0.5f * sinf(s);
    }
    if (tid >= 96 && tid < 96 + SS * SS) {
        int t = tid - 96;
        int r = t / SS, c = t % SS;
        int lo = min(r, c), hi = max(r, c);
        ptab[t] = lo * SS - (lo * (lo - 1)) / 2 + (hi - lo);
    }
    if (tid == 64) {
        s_etaR = EtaR[0];
        s_etaA = EtaA[0];
        s_zeta = Zeta[0];
        nnb[0] = 0;
        nnb[1] = 0;
    }
    if (tid < NATB * SS * RAD_SUB) ((float*)accR)[tid] = 0.0f;
    if (tid >= 72 && tid < 72 + NBUCK) bcnt[tid - 72] = 0;
    __syncthreads();

    // ---- ladder ratio tables ----
    if (tid < NSHFR - 1) {
        const float k = s_etaR * (shfR[1] - shfR[0]);
        const float ss = shfR[tid] + shfR[tid + 1];
        cuR[tid] = __expf(-k * ss);
        cdR[tid] = __expf( k * ss);
    }
    if (tid >= 32 && tid < 32 + NSHFA - 1) {
        const int t = tid - 32;
        const float k = s_etaA * (shfA_s[1] - shfA_s[0]);
        cauA[t] = __expf(-k * (shfA_s[t] + shfA_s[t + 1]));
    }
    if (tid == 64) {
        const float dR = shfR[1] - shfR[0];
        s_invdR = 1.0f / dR;
        s_2edR  = 2.0f * s_etaR * dR;
        s_2edA  = 2.0f * s_etaA * (shfA_s[1] - shfA_s[0]);
    }
    __syncthreads();

    // ---- radial (Gaussian ladder) + neighbor list build, 2 atoms ----
    if (tid < 2 * AA) {
        const int j  = tid >> 1;
        const int at = tid & 1;
        const int ci = cb + at;
        if (j != ci) {
            const float cxi = scrd[3 * ci + 0];
            const float cyi = scrd[3 * ci + 1];
            const float czi = scrd[3 * ci + 2];
            const float dx = scrd[3 * j + 0] - cxi;
            const float dy = scrd[3 * j + 1] - cyi;
            const float dz = scrd[3 * j + 2] - czi;
            const float d2s = dx * dx + dy * dy + dz * dz;
            const float d   = d2s * rsqrtf(fmaxf(d2s, 1e-24f));

            if (d <= RCR_F) {
                const float fc   = 0.5f * __cosf(d * (float)(M_PI / 5.2)) + 0.5f;
                const float base = 0.25f * fc;
                const int   off  = ssp[j] * RAD_SUB;
                const float eR   = s_etaR;
                const float s0   = shfR[0];
                const float dR   = shfR[1] - s0;

                int ts = (int)floorf(fmaf(d - s0, s_invdR, 0.5f));
                ts = min(NSHFR - 1, max(0, ts));
                const float x = d - fmaf((float)ts, dR, s0);
                float f = base * __expf(-eR * x * x);
                atomicAdd(&accR[at][off + ts], f);

                const float R    = __expf(s_2edR * d);
                const float Rinv = __fdividef(1.0f, R);

                float fu = f;
                #pragma unroll
                for (int k = 1; k <= 5; k++) {
                    const int t = ts + k;
                    if (t > NSHFR - 1) break;
                    fu *= R * cuR[t - 1];
                    atomicAdd(&accR[at][off + t], fu);
                }
                float fd = f;
                #pragma unroll
                for (int k = 1; k <= 5; k++) {
                    const int t = ts - k;
                    if (t < 0) break;
                    fd *= Rinv * cdR[t];
                    atomicAdd(&accR[at][off + t], fd);
                }
            }
            if (d <= RCA_F) {
                const int slot = atomicAdd(&nnb[at], 1);
                nbd[at][slot]  = d;
                nbx[at][slot]  = dx;
                nby[at][slot]  = dy;
                nbz[at][slot]  = dz;
                nbfc[at][slot] = 1.41421356237f * (0.5f * __cosf(d * (float)(M_PI / 3.5)) + 0.5f);
                nbsp[at][slot] = ssp[j];
            }
        }
    }
    __syncthreads();

    const int n0 = nnb[0], n1 = nnb[1];
    const int npair0 = n0 * (n0 - 1) / 2;
    const int npair1 = n1 * (n1 - 1) / 2;
    const int npair  = npair0 + npair1;

    // ---- build explicit pair list for both atoms ----
    {
        const int at = (tid < 64) ? 0 : 1;
        const int a  = (tid < 64) ? tid : tid - 64;
        const int nA = (at == 0) ? n0 : n1;
        const int pb = (at == 0) ? 0 : npair0;
        if (a < nA - 1) {
            int w = pb + ((a * (2 * nA - a - 1)) >> 1);
            const unsigned short tag = (unsigned short)((at << 13) | a);
            for (int b = a + 1; b < nA; b++)
                ppair[w++] = (unsigned short)(tag | (b << 6));
        }
    }
    __syncthreads();

    const float etaA = s_etaA;
    const float zeta = s_zeta;
    const bool  z32  = (zeta == 32.0f);

    // ---- channel ownership: 640 channels = 5 per thread ----
    // ch_k = tid + 128k.  Since 128 % 32 == 0: iz = tid&7 and ia = (tid>>3)&3
    // are IDENTICAL for all 5 slots; only (atom, pidx) differ (warp-uniform).
    const int iz  = tid & 7;
    const int ia_ = (tid >> 3) & 3;
    const float rcz = cz2[iz], rsz = sz2[iz];

    int bk[5];
    #pragma unroll
    for (int k = 0; k < 5; k++) {
        const int ch   = tid + k * NTHREADS;
        const int atom = ch / NANG;
        const int px   = (ch - atom * NANG) >> 5;
        bk[k] = atom * NPAIRS_SP + px;
    }
    float av[5] = {0.0f, 0.0f, 0.0f, 0.0f, 0.0f};

    for (int base = 0; base < npair; base += NTHREADS) {
        const int cnt = min(npair - base, NTHREADS);

        // ---- Phase A: one thread per pair -> record + bucket push ----
        if (tid < cnt) {
            const unsigned short pr = ppair[base + tid];
            const int a  = pr & 63;
            const int b  = (pr >> 6) & 63;
            const int at = pr >> 13;

            const float d1 = nbd[at][a], d2 = nbd[at][b];
            const float inv = __fdividef(1.0f, fmaxf(d1 * d2, 1e-16f));
            const float dot = nbx[at][a] * nbx[at][b] + nby[at][a] * nby[at][b]
                            + nbz[at][a] * nbz[at][b];
            const float c   = 0.95f * dot * inv;
            const float omc = 1.0f - c * c;               // >= 0.0975
            const float sn  = omc * rsqrtf(omc);

            const float fcj2 = nbfc[at][a] * nbfc[at][b];  // = 2*fc1*fc2
            const float dm   = 0.5f * (d1 + d2);

            pc[tid]  = c;
            psn[tid] = sn;

            const float xa = dm - shfA_s[0];
            float f  = __expf(-etaA * xa * xa) * fcj2;
            const float RA = __expf(s_2edA * dm);
            pf2[tid][0] = f;
            f *= RA * cauA[0]; pf2[tid][1] = f;
            f *= RA * cauA[1]; pf2[tid][2] = f;
            f *= RA * cauA[2]; pf2[tid][3] = f;

            const int pidx = ptab[nbsp[at][a] * SS + nbsp[at][b]];
            const int bkt  = at * NPAIRS_SP + pidx;
            const int pos  = atomicAdd(&bcnt[bkt], 1);
            blist[bkt][pos] = tid;
        }
        __syncthreads();

        // ---- Phase B: 5 bucket scans (warp-uniform, broadcast LDS) ----
        #pragma unroll
        for (int k = 0; k < 5; k++) {
            const int bkt = bk[k];
            const int cn  = bcnt[bkt];
            float accv = av[k];
            for (int e = 0; e < cn; e++) {
                const int s = blist[bkt][e];
                float t = fmaf(pc[s], rcz, fmaf(psn[s], rsz, 0.5f));
                if (z32) { t = t*t; t = t*t; t = t*t; t = t*t; t = t*t; }
                else     { t = __powf(t, zeta); }
                accv = fmaf(t, pf2[s][ia_], accv);
            }
            av[k] = accv;
        }
        // only pay barriers/reset if another tile follows
        if (base + NTHREADS < npair) {
            __syncthreads();
            if (tid < NBUCK) bcnt[tid] = 0;
            __syncthreads();
        }
    }

    // ---- write out ----
    // radial: 2 atoms x 64 channels
    {
        const int at = tid >> 6;
        const int c  = tid & 63;
        out[(size_t)(m * AA + cb + at) * OUT_PER_ATOM + c] = accR[at][c];
    }
    // angular: 5 slots per thread
    #pragma unroll
    for (int k = 0; k < 5; k++) {
        const int ch   = tid + k * NTHREADS;
        const int atom = ch / NANG;
        const int cc   = ch - atom * NANG;
        out[(size_t)(m * AA + cb + atom) * OUT_PER_ATOM + SS * RAD_SUB + cc] = av[k];
    }
}

extern "C" void kernel_launch(void* const* d_in, const int* in_sizes, int n_in,
                              void* d_out, int out_size)
{
    const float* coords  = (const float*)d_in[0];
    const float* EtaR    = (const float*)d_in[1];
    const float* ShfR    = (const float*)d_in[2];
    const float* EtaA    = (const float*)d_in[3];
    const float* Zeta    = (const float*)d_in[4];
    const float* ShfA    = (const float*)d_in[5];
    const float* ShfZ    = (const float*)d_in[6];
    const int*   species = (const int*)d_in[7];
    float* out = (float*)d_out;

    aev_kernel<<<MM * AA / NATB, NTHREADS>>>(coords, EtaR, ShfR, EtaA, Zeta,
                                             ShfA, ShfZ, species, out);
}

// round 12
// speedup vs baseline: 1.4570x; 1.4570x over previous
#include <cuda_runtime.h>
#include <math.h>

// ANI AEV computer. M=32, A=48, S=4.
// Radial: 4 species x 16 ShfR = 64 ch. Angular: 10 sp-pairs x 4 ShfA x 8 ShfZ = 320 ch.
// Output (32, 48, 384) fp32.
//
// R7 (15.0us): bucketed gather (zero angular atomics).
// R8 (14.0us): Gaussian-ladder exp factorization.
// R9 (12.8us): shared pair list, vectorized prologue, fewer syncs.
// R10 FAILED: 2 atoms/block halved resident blocks -> keep grid 1536x128.
// R11: zeta-power hoisted to Phase A (8 g[iz] per pair, computed once instead
//      of per-channel): Phase B = 2 broadcast LDS + 1 FMA per entry. Single-sync
//      prologue (tables built from global). Slot-uniform iz/ia (128 = 0 mod 32).

#define MM 32
#define AA 48
#define SS 4
#define NSHFR 16
#define NSHFA 4
#define NSHFZ 8
#define RAD_SUB 16
#define ANG_SUB 32
#define NPAIRS_SP 10
#define NANG (NPAIRS_SP * ANG_SUB)                 // 320
#define OUT_PER_ATOM (SS * RAD_SUB + NANG)         // 384
#define RCR_F 5.2f
#define RCA_F 3.5f
#define NTHREADS 128
#define MAXPAIR 1128                               // 47*46/2 + pad

__global__ __launch_bounds__(NTHREADS)
void aev_kernel(const float* __restrict__ coords,
                const float* __restrict__ EtaR,
                const float* __restrict__ ShfR,
                const float* __restrict__ EtaA,
                const float* __restrict__ Zeta,
                const float* __restrict__ ShfA,
                const float* __restrict__ ShfZ,
                const int*   __restrict__ species,
                float*       __restrict__ out)
{
    const int m   = blockIdx.x / AA;
    const int ci  = blockIdx.x % AA;
    const int tid = threadIdx.x;

    __shared__ float scrd[AA * 3];
    __shared__ int   ssp[AA];
    __shared__ float accR[SS * RAD_SUB];
    __shared__ float shfR[NSHFR], shfA_s[NSHFA];
    __shared__ float cz2[NSHFZ], sz2[NSHFZ];        // 0.5*cos(ShfZ), 0.5*sin(ShfZ)
    __shared__ int   ptab[SS * SS];
    __shared__ float s_etaR, s_etaA, s_zeta;
    __shared__ float s_invdR, s_2edR, s_2edA;
    __shared__ int   nnb;
    __shared__ float nbd[AA], nbx[AA], nby[AA], nbz[AA], nbfc[AA];
    __shared__ int   nbsp[AA];
    __shared__ float cuR[NSHFR - 1], cdR[NSHFR - 1], cauA[NSHFA - 1];
    __shared__ unsigned short ppair[MAXPAIR];
    // per-tile pair records + buckets
    __shared__ float g8[NTHREADS][NSHFZ];           // zeta-powered angle terms
    __shared__ float pf2[NTHREADS][NSHFA];          // radial-envelope terms
    __shared__ int   blist[NPAIRS_SP][NTHREADS];
    __shared__ int   bcnt[NPAIRS_SP];

    // ---- SINGLE-SYNC prologue: everything built from global loads ----
    if (tid < 36)
        ((float4*)scrd)[tid] = ((const float4*)(coords + m * AA * 3))[tid];
    if (tid >= 40 && tid < 52)
        ((int4*)ssp)[tid - 40] = ((const int4*)(species + m * AA))[tid - 40];
    if (tid < NSHFR) shfR[tid] = ShfR[tid];
    if (tid < NSHFA) shfA_s[tid] = ShfA[tid];
    if (tid < NSHFZ) {
        float s = ShfZ[tid];
        cz2[tid] = 0.5f * cosf(s);
        sz2[tid] = 0.5f * sinf(s);
    }
    if (tid < NSHFR - 1) {                          // radial ladder ratios (from global)
        const float k = EtaR[0] * (ShfR[1] - ShfR[0]);
        const float ss = ShfR[tid] + ShfR[tid + 1];
        cuR[tid] = __expf(-k * ss);
        cdR[tid] = __expf( k * ss);
    }
    if (tid >= 32 && tid < 32 + NSHFA - 1) {        // angular ladder ratios
        const int t = tid - 32;
        const float k = EtaA[0] * (ShfA[1] - ShfA[0]);
        cauA[t] = __expf(-k * (ShfA[t] + ShfA[t + 1]));
    }
    if (tid >= 96 && tid < 96 + SS * SS) {
        int t = tid - 96;
        int r = t / SS, c = t % SS;
        int lo = min(r, c), hi = max(r, c);
        ptab[t] = lo * SS - (lo * (lo - 1)) / 2 + (hi - lo);
    }
    if (tid == 64) {
        s_etaR = EtaR[0];
        s_etaA = EtaA[0];
        s_zeta = Zeta[0];
        const float dR = ShfR[1] - ShfR[0];
        s_invdR = 1.0f / dR;
        s_2edR  = 2.0f * EtaR[0] * dR;
        s_2edA  = 2.0f * EtaA[0] * (ShfA[1] - ShfA[0]);
        nnb = 0;
    }
    if (tid < SS * RAD_SUB) accR[tid] = 0.0f;
    if (tid >= 72 && tid < 72 + NPAIRS_SP) bcnt[tid - 72] = 0;
    __syncthreads();

    const float cxi = scrd[3 * ci + 0];
    const float cyi = scrd[3 * ci + 1];
    const float czi = scrd[3 * ci + 2];

    // ---- radial (Gaussian ladder) + neighbor list build ----
    if (tid < AA && tid != ci) {
        const int j = tid;
        const float dx = scrd[3 * j + 0] - cxi;
        const float dy = scrd[3 * j + 1] - cyi;
        const float dz = scrd[3 * j + 2] - czi;
        const float d2s = dx * dx + dy * dy + dz * dz;
        const float d   = d2s * rsqrtf(fmaxf(d2s, 1e-24f));

        if (d <= RCR_F) {
            const float fc   = 0.5f * __cosf(d * (float)(M_PI / 5.2)) + 0.5f;
            const float base = 0.25f * fc;
            const int   off  = ssp[j] * RAD_SUB;
            const float eR   = s_etaR;
            const float s0   = shfR[0];
            const float dR   = shfR[1] - s0;

            int ts = (int)floorf(fmaf(d - s0, s_invdR, 0.5f));
            ts = min(NSHFR - 1, max(0, ts));
            const float x = d - fmaf((float)ts, dR, s0);
            float f = base * __expf(-eR * x * x);
            atomicAdd(&accR[off + ts], f);

            const float R    = __expf(s_2edR * d);
            const float Rinv = __fdividef(1.0f, R);

            float fu = f;
            #pragma unroll
            for (int k = 1; k <= 5; k++) {
                const int t = ts + k;
                if (t > NSHFR - 1) break;
                fu *= R * cuR[t - 1];
                atomicAdd(&accR[off + t], fu);
            }
            float fd = f;
            #pragma unroll
            for (int k = 1; k <= 5; k++) {
                const int t = ts - k;
                if (t < 0) break;
                fd *= Rinv * cdR[t];
                atomicAdd(&accR[off + t], fd);
            }
        }
        if (d <= RCA_F) {
            const int slot = atomicAdd(&nnb, 1);
            nbd[slot]  = d;
            nbx[slot]  = dx;
            nby[slot]  = dy;
            nbz[slot]  = dz;
            nbfc[slot] = 1.41421356237f * (0.5f * __cosf(d * (float)(M_PI / 3.5)) + 0.5f);
            nbsp[slot] = ssp[j];
        }
    }
    __syncthreads();

    const int n     = nnb;
    const int npair = n * (n - 1) / 2;

    // ---- build explicit pair list (rowstart is closed-form) ----
    if (tid < n - 1) {
        const int a = tid;
        int w = (a * (2 * n - a - 1)) >> 1;
        for (int b = a + 1; b < n; b++)
            ppair[w++] = (unsigned short)(a | (b << 8));
    }
    __syncthreads();

    const float etaA = s_etaA;
    const float zeta = s_zeta;
    const bool  z32  = (zeta == 32.0f);

    // ---- channel ownership: iz/ia identical across a thread's 3 slots ----
    const int iz  = tid & 7;
    const int ia_ = (tid >> 3) & 3;
    const int px0 = tid >> 5;          // slot buckets: px0, px0+4, px0+8
    const bool has2 = (tid < NANG - 256);   // tid < 64

    float a0 = 0.0f, a1 = 0.0f, a2 = 0.0f;

    for (int base = 0; base < npair; base += NTHREADS) {
        const int cnt = min(npair - base, NTHREADS);

        // ---- Phase A: one thread per pair -> g8[8], pf2[4], bucket push ----
        if (tid < cnt) {
            const unsigned short pr = ppair[base + tid];
            const int a = pr & 0xFF;
            const int b = pr >> 8;

            const float d1 = nbd[a], d2 = nbd[b];
            const float inv = __fdividef(1.0f, fmaxf(d1 * d2, 1e-16f));
            const float dot = nbx[a] * nbx[b] + nby[a] * nby[b] + nbz[a] * nbz[b];
            const float c   = 0.95f * dot * inv;
            const float omc = 1.0f - c * c;               // >= 0.0975
            const float sn  = omc * rsqrtf(omc);

            const float fcj2 = nbfc[a] * nbfc[b];          // = 2*fc1*fc2
            const float dm   = 0.5f * (d1 + d2);

            // angular Gaussian ladder: 2 MUFU for all 4 ShfA terms
            const float xa = dm - shfA_s[0];
            float f  = __expf(-etaA * xa * xa) * fcj2;
            const float RA = __expf(s_2edA * dm);
            float4 ff;
            ff.x = f;
            f *= RA * cauA[0]; ff.y = f;
            f *= RA * cauA[1]; ff.z = f;
            f *= RA * cauA[2]; ff.w = f;
            *(float4*)pf2[tid] = ff;

            // zeta-powered angle terms, once per pair (not per channel)
            float4 glo, ghi;
            #pragma unroll
            for (int z = 0; z < NSHFZ; z++) {
                float t = fmaf(c, cz2[z], fmaf(sn, sz2[z], 0.5f));
                if (z32) { t = t*t; t = t*t; t = t*t; t = t*t; t = t*t; }
                else     { t = __powf(t, zeta); }
                if (z == 0) glo.x = t; else if (z == 1) glo.y = t;
                else if (z == 2) glo.z = t; else if (z == 3) glo.w = t;
                else if (z == 4) ghi.x = t; else if (z == 5) ghi.y = t;
                else if (z == 6) ghi.z = t; else ghi.w = t;
            }
            *(float4*)&g8[tid][0] = glo;
            *(float4*)&g8[tid][4] = ghi;

            const int pidx = ptab[nbsp[a] * SS + nbsp[b]];
            const int pos  = atomicAdd(&bcnt[pidx], 1);
            blist[pidx][pos] = tid;
        }
        __syncthreads();

        // ---- Phase B: 2 LDS + 1 FMA per bucket entry ----
        {
            const int c0n = bcnt[px0];
            for (int e = 0; e < c0n; e++) {
                const int s = blist[px0][e];
                a0 = fmaf(g8[s][iz], pf2[s][ia_], a0);
            }
            const int c1n = bcnt[px0 + 4];
            for (int e = 0; e < c1n; e++) {
                const int s = blist[px0 + 4][e];
                a1 = fmaf(g8[s][iz], pf2[s][ia_], a1);
            }
            if (has2) {
                const int c2n = bcnt[px0 + 8];
                for (int e = 0; e < c2n; e++) {
                    const int s = blist[px0 + 8][e];
                    a2 = fmaf(g8[s][iz], pf2[s][ia_], a2);
                }
            }
        }
        // only pay barriers/reset if another tile follows (npair > 128 is rare)
        if (base + NTHREADS < npair) {
            __syncthreads();
            if (tid < NPAIRS_SP) bcnt[tid] = 0;
            __syncthreads();
        }
    }

    // ---- write out ----
    float* o = out + (size_t)(m * AA + ci) * OUT_PER_ATOM;
    if (tid < SS * RAD_SUB) o[tid] = accR[tid];
    o[SS * RAD_SUB + tid]       = a0;
    o[SS * RAD_SUB + tid + 128] = a1;
    if (has2) o[SS * RAD_SUB + tid + 256] = a2;
}

extern "C" void kernel_launch(void* const* d_in, const int* in_sizes, int n_in,
                              void* d_out, int out_size)
{
    const float* coords  = (const float*)d_in[0];
    const float* EtaR    = (const float*)d_in[1];
    const float* ShfR    = (const float*)d_in[2];
    const float* EtaA    = (const float*)d_in[3];
    const float* Zeta    = (const float*)d_in[4];
    const float* ShfA    = (const float*)d_in[5];
    const float* ShfZ    = (const float*)d_in[6];
    const int*   species = (const int*)d_in[7];
    float* out = (float*)d_out;

    aev_kernel<<<MM * AA, NTHREADS>>>(coords, EtaR, ShfR, EtaA, Zeta,
                                      ShfA, ShfZ, species, out);
}